// round 16
// baseline (speedup 1.0000x reference)
#include <cuda_runtime.h>
#include <math.h>

#define NB 8
#define NC 19
#define HW (512 * 512)
#define HW4 (HW / 4)
#define SMOOTH 1e-08f
#define GRID_X 56
#define NBLOCKS (GRID_X * NB)
#define NTHREADS 128
#define STRIDE (GRID_X * NTHREADS)

__device__ float g_acc[2 * NB * NC];   // [0..152)=tp, [152..304)=den
__device__ unsigned int g_done = 0;

__device__ __forceinline__ float ex2f(float x) {
    asm("ex2.approx.f32 %0, %0;" : "+f"(x));
    return x;
}
// 2KB contiguous L2 prefetch
__device__ __forceinline__ void pf_bulk2k(const void* p) {
    asm volatile("cp.async.bulk.prefetch.L2.global [%0], 2048;"
                 :: "l"(p) : "memory");
}

__global__ __launch_bounds__(NTHREADS, 3) void tversky_fused_kernel(
    const float* __restrict__ pred, const int* __restrict__ target,
    float* __restrict__ out) {
    const int b = blockIdx.y;
    const float4* __restrict__ p4 =
        (const float4*)(pred + (size_t)b * NC * HW);
    const int4* __restrict__ t4 = (const int4*)(target + (size_t)b * HW);
    const int tid = threadIdx.x;

    __shared__ float s_acc[2 * NC];   // tp, den
    __shared__ int s_is_last;
    if (tid < 2 * NC) s_acc[tid] = 0.0f;
    __syncthreads();

    float rtp[NC], rden[NC];
#pragma unroll
    for (int c = 0; c < NC; c++) { rtp[c] = 0.0f; rden[c] = 0.0f; }

    const int base0 = blockIdx.x * NTHREADS;

    // prologue: warm iteration-1's tiles (iteration 0 pays the cold miss)
    {
        const int pb = base0 + STRIDE;
        if (pb < HW4) {
            if (tid < NC)       pf_bulk2k(p4 + (size_t)tid * HW4 + pb);
            else if (tid == NC) pf_bulk2k(t4 + pb);
        }
    }

    const float LOG2E = 1.4426950408889634f;
    for (int idx = base0 + tid; idx < HW4; idx += STRIDE) {
        float4 e[NC];
#pragma unroll
        for (int c = 0; c < NC; c++) e[c] = __ldcs(&p4[(size_t)c * HW4 + idx]);
        const int4 tg = __ldcs(&t4[idx]);

        // bulk prefetch stream, 2 grid-strides ahead (one warp, 20 x 2KB):
        // keeps DRAM row-open requests flowing during the compute phase
        {
            const int pb = (idx - tid) + 2 * STRIDE;
            if (pb < HW4) {
                if (tid < NC)       pf_bulk2k(p4 + (size_t)tid * HW4 + pb);
                else if (tid == NC) pf_bulk2k(t4 + pb);
            }
        }

        float sx = 0.0f, sy = 0.0f, sz = 0.0f, sw = 0.0f;
#pragma unroll
        for (int c = 0; c < NC; c++) {
            e[c].x = ex2f(e[c].x * LOG2E);
            e[c].y = ex2f(e[c].y * LOG2E);
            e[c].z = ex2f(e[c].z * LOG2E);
            e[c].w = ex2f(e[c].w * LOG2E);
            sx += e[c].x; sy += e[c].y; sz += e[c].z; sw += e[c].w;
        }
        const float rx = __fdividef(1.0f, sx);
        const float ry = __fdividef(1.0f, sy);
        const float rz = __fdividef(1.0f, sz);
        const float rw = __fdividef(1.0f, sw);

#pragma unroll
        for (int c = 0; c < NC; c++) {
            rden[c] = fmaf(e[c].x, rx, rden[c]);
            rden[c] = fmaf(e[c].y, ry, rden[c]);
            rden[c] = fmaf(e[c].z, rz, rden[c]);
            rden[c] = fmaf(e[c].w, rw, rden[c]);
            if (tg.x == c) { rtp[c] = fmaf(e[c].x, rx, rtp[c]); rden[c] += 1.0f; }
            if (tg.y == c) { rtp[c] = fmaf(e[c].y, ry, rtp[c]); rden[c] += 1.0f; }
            if (tg.z == c) { rtp[c] = fmaf(e[c].z, rz, rtp[c]); rden[c] += 1.0f; }
            if (tg.w == c) { rtp[c] = fmaf(e[c].w, rw, rtp[c]); rden[c] += 1.0f; }
        }
    }

    // warp-level reduction of the 38 accumulators
#pragma unroll
    for (int c = 0; c < NC; c++) {
#pragma unroll
        for (int off = 16; off > 0; off >>= 1) {
            rtp[c]  += __shfl_down_sync(0xFFFFFFFFu, rtp[c],  off);
            rden[c] += __shfl_down_sync(0xFFFFFFFFu, rden[c], off);
        }
    }
    if ((tid & 31) == 0) {
#pragma unroll
        for (int c = 0; c < NC; c++) {
            atomicAdd(&s_acc[c], rtp[c]);
            atomicAdd(&s_acc[NC + c], rden[c]);
        }
    }
    __syncthreads();

    // block -> global (38 atomics from first 38 threads)
    if (tid < 2 * NC) {
        const int sec = tid / NC;
        const int c = tid - sec * NC;
        atomicAdd(&g_acc[sec * NB * NC + b * NC + c], s_acc[tid]);
    }

    // last-block-done epilogue
    __threadfence();
    if (tid == 0) {
        unsigned int n = atomicAdd(&g_done, 1u);
        s_is_last = (n == NBLOCKS - 1);
    }
    __syncthreads();
    if (!s_is_last) return;

    __shared__ float s_red[NTHREADS];
    float v = 0.0f;
#pragma unroll
    for (int k = 0; k < 2; k++) {           // NB*NC = 152 > 128 threads
        const int i = tid + k * NTHREADS;
        if (i < NB * NC) {
            const float tp = __ldcg(&g_acc[i]);
            const float dn = __ldcg(&g_acc[NB * NC + i]);
            v += 1.0f - (tp + SMOOTH) / (0.5f * dn + SMOOTH);  // alpha=beta=0.5
        }
    }
    s_red[tid] = v;
    __syncthreads();
#pragma unroll
    for (int off = NTHREADS / 2; off > 0; off >>= 1) {
        if (tid < off) s_red[tid] += s_red[tid + off];
        __syncthreads();
    }
    if (tid == 0) {
        out[0] = s_red[0] / (float)(NB * NC);
        g_done = 0u;
    }
    for (int i = tid; i < 2 * NB * NC; i += NTHREADS) g_acc[i] = 0.0f;
}

extern "C" void kernel_launch(void* const* d_in, const int* in_sizes, int n_in,
                              void* d_out, int out_size) {
    const float* pred = (const float*)d_in[0];
    const int* target = (const int*)d_in[1];
    float* out = (float*)d_out;

    dim3 grid(GRID_X, NB);
    tversky_fused_kernel<<<grid, NTHREADS>>>(pred, target, out);
}